// round 15
// baseline (speedup 1.0000x reference)
#include <cuda_runtime.h>
#include <math.h>
#include <stdint.h>

#define B_DIM 32
#define T_SEQ 512
#define D_DIM 512
#define U_DIM 512
#define NG    2048                 // 4*U
#define M_TOT (B_DIM * T_SEQ)     // 16384

// ---------------- scratch (static device memory; no allocations) ----------------
__device__ float g_xg[2][B_DIM][T_SEQ][NG];        // input projections, both dirs (256 MB)
__device__ float g_hbuf[2][2][B_DIM][U_DIM];       // h double buffers (k-PERMUTED, tf32-rounded)
__device__ float g_hb_out[B_DIM][T_SEQ][U_DIM];    // backward-direction outputs
__device__ float g_xT[D_DIM][M_TOT];               // tf32-rounded x, TRANSPOSED [k][m] (32 MB)
__device__ float g_Wc[2][D_DIM][NG];               // tf32-rounded W copies [dir][k][n] (16 MB)

// h-chunk barrier (R9, proven): chunk c = producer CTAs blk 16c..16c+15. Padded
// lines, monotonic across graph replays.
__device__ unsigned g_chcnt[2][4][32];             // [dir][chunk][pad] arrival counters
__device__ volatile unsigned g_chep[2][4][32];     // [dir][chunk][pad] chunk epochs

// xg-readiness counters: [dir][t-chunk of 128 steps], 512 GEMM-tile arrivals each.
// RESET to 0 at the start of every replay (reset_xg runs before the fork).
__device__ unsigned g_xgcnt[2][4][32];

#define NCTA_DIR    64
#define REC_THREADS 256

// ---------------- tf32 helpers ----------------
__device__ __forceinline__ unsigned f2tf32(float f)
{
    unsigned r;
    asm("cvt.rna.tf32.f32 %0, %1;" : "=r"(r) : "f"(f));
    return r;
}
__device__ __forceinline__ float tf32f(float f) { return __uint_as_float(f2tf32(f)); }

// D += A@B, m16n8k8, A row-major, B col-major, tf32 in / fp32 accum
__device__ __forceinline__ void mma8(float* c,
                                     unsigned a0, unsigned a1, unsigned a2, unsigned a3,
                                     unsigned b0, unsigned b1)
{
    asm("mma.sync.aligned.m16n8k8.row.col.f32.tf32.tf32.f32 "
        "{%0,%1,%2,%3},{%4,%5,%6,%7},{%8,%9},{%0,%1,%2,%3};"
        : "+f"(c[0]), "+f"(c[1]), "+f"(c[2]), "+f"(c[3])
        : "r"(a0), "r"(a1), "r"(a2), "r"(a3), "r"(b0), "r"(b1));
}

// k-permutation within each 8-block: (pi(k),pi(k)+1) consecutive = (k, k+4)
__device__ __forceinline__ int perm8(int k)
{
    return (k & ~7) | ((k & 3) << 1) | ((k & 7) >> 2);
}

// ---------------- fast transcendentals (MUFU-based, saturation-safe) ----------------
__device__ __forceinline__ float fsigm(float x)
{
    return __fdividef(1.0f, 1.0f + __expf(-x));
}
__device__ __forceinline__ float ftanh(float x)
{
    return 1.0f - __fdividef(2.0f, 1.0f + __expf(2.0f * x));
}

// ---------------- release/acquire barrier primitives (no full MEMBAR) ----------------
__device__ __forceinline__ void ch_arrive(int dir, int chunk, unsigned ep_next)
{
    unsigned v;
    asm volatile("atom.add.release.gpu.u32 %0, [%1], %2;"
                 : "=r"(v)
                 : "l"((unsigned*)&g_chcnt[dir][chunk][0]), "r"(1u)
                 : "memory");
    if ((v & 15u) == 15u)
        asm volatile("st.release.gpu.u32 [%0], %1;"
                     :: "l"((unsigned*)&g_chep[dir][chunk][0]), "r"(ep_next)
                     : "memory");
}

__device__ __forceinline__ void ch_wait(int dir, int ck, unsigned ep0, unsigned need)
{
    unsigned cur;
    do {
        asm volatile("ld.acquire.gpu.u32 %0, [%1];"
                     : "=r"(cur)
                     : "l"((const unsigned*)&g_chep[dir][ck][0])
                     : "memory");
    } while (cur - ep0 < need);
}

// =================================================================================
// Pre-pass 1: x[m][k] -> g_xT[k][m], tf32-rounded (smem tile transpose)
// =================================================================================
__global__ void cvt_xT(const float* __restrict__ X)
{
    __shared__ float t[32][33];
    const int kb = blockIdx.x * 32;
    const int mb = blockIdx.y * 32;
    const int tx = threadIdx.x, ty = threadIdx.y;
    #pragma unroll
    for (int i = ty; i < 32; i += 8)
        t[i][tx] = X[(size_t)(mb + i) * D_DIM + kb + tx];
    __syncthreads();
    #pragma unroll
    for (int i = ty; i < 32; i += 8)
        g_xT[kb + i][mb + tx] = tf32f(t[tx][i]);
}

// =================================================================================
// Pre-pass 2: W[dir][k][n] tf32-rounded straight copy
// =================================================================================
__global__ void cvt_W(const float* __restrict__ Wf, const float* __restrict__ Wb)
{
    const int n4 = D_DIM * NG / 4;
    int i = blockIdx.x * blockDim.x + threadIdx.x;
    if (i < 2 * n4) {
        int dir = i >= n4;
        int j = dir ? i - n4 : i;
        float4 v = ((const float4*)(dir ? Wb : Wf))[j];
        v.x = tf32f(v.x); v.y = tf32f(v.y); v.z = tf32f(v.z); v.w = tf32f(v.w);
        ((float4*)&g_Wc[dir][0][0])[j] = v;
    }
}

// =================================================================================
// Reset xg-readiness counters (runs before the fork every replay — deterministic)
// =================================================================================
__global__ void reset_xg()
{
    int i = threadIdx.x;
    if (i < 8) g_xgcnt[i >> 2][i & 3][0] = 0u;
}

// =================================================================================
// Kernel A: xg GEMM (R9 cp.async version), PRIORITY-ORDERED 1-D grid + arrival.
// bid decode: g=prio group 0..3; within: dir, b(32), n-tile(16). t-chunk = g for
// fwd, 3-g for bwd, so earliest-scheduled CTAs produce what the recurrence
// consumes first. After its stores each CTA release-arrives on g_xgcnt[dir][tch].
// =================================================================================
#define GS 136
#define GSMEM (3 * 16 * GS * 4 * 2)                // 52,224 B

__global__ __launch_bounds__(256, 2) void gemm_xg(
    const float* __restrict__ bf, const float* __restrict__ bb)
{
    extern __shared__ float gsm[];
    float* As = gsm;                   // [3][16][GS]
    float* Bs = gsm + 3 * 16 * GS;     // [3][16][GS]

    // priority decode
    const int bidx = blockIdx.x;               // 0..4095
    const int pg   = bidx >> 10;               // 0..3
    const int r    = bidx & 1023;
    const int dir  = r >> 9;
    const int q    = r & 511;
    const int bb_i = q & 31;                   // batch
    const int nt   = q >> 5;                   // 0..15
    const int tch  = dir ? (3 - pg) : pg;      // t-chunk this CTA produces
    const int mBase = bb_i * T_SEQ + tch * 128;
    const int nBase = nt * 128;

    const float* __restrict__ bias = dir ? bb : bf;

    const int tid   = threadIdx.x;
    const int lane  = tid & 31, wid = tid >> 5;
    const int gid   = lane >> 2, tig = lane & 3;
    const int m0w   = (wid & 1) * 64;
    const int n0w   = (wid >> 1) * 32;

    const unsigned As_s = (unsigned)__cvta_generic_to_shared(As);
    const unsigned Bs_s = (unsigned)__cvta_generic_to_shared(Bs);
    const float* Wd = &g_Wc[dir][0][0];

    auto stage = [&](int buf, int kt) {
        #pragma unroll
        for (int j = 0; j < 2; j++) {
            int ca  = tid + j * 256;
            int row = ca >> 5;
            int c16 = (ca & 31) * 4;
            const float* srcA = &g_xT[kt + row][mBase + c16];
            const float* srcB = Wd + (size_t)(kt + row) * NG + nBase + c16;
            unsigned dA = As_s + (unsigned)((buf * 16 + row) * GS + c16) * 4u;
            unsigned dB = Bs_s + (unsigned)((buf * 16 + row) * GS + c16) * 4u;
            asm volatile("cp.async.cg.shared.global [%0], [%1], 16;" :: "r"(dA), "l"(srcA));
            asm volatile("cp.async.cg.shared.global [%0], [%1], 16;" :: "r"(dB), "l"(srcB));
        }
        asm volatile("cp.async.commit_group;");
    };

    float acc[4][4][4];
    #pragma unroll
    for (int i = 0; i < 4; i++)
        #pragma unroll
        for (int j = 0; j < 4; j++)
            #pragma unroll
            for (int qq = 0; qq < 4; qq++) acc[i][j][qq] = 0.0f;

    stage(0, 0);
    stage(1, 16);

    int cur = 0;
    for (int kt = 0; kt < D_DIM; kt += 16) {
        if (kt + 32 < D_DIM) asm volatile("cp.async.wait_group 1;");
        else                 asm volatile("cp.async.wait_group 0;");
        __syncthreads();
        if (kt + 32 < D_DIM) stage((cur + 2) % 3, kt + 32);

        const float* Ab = As + cur * 16 * GS;
        const float* Bb = Bs + cur * 16 * GS;
        #pragma unroll
        for (int kk = 0; kk < 16; kk += 8) {
            unsigned af[4][4], bfr[4][2];
            #pragma unroll
            for (int mf = 0; mf < 4; mf++) {
                int mr = m0w + mf * 16 + gid;
                af[mf][0] = __float_as_uint(Ab[(kk + tig) * GS + mr]);
                af[mf][1] = __float_as_uint(Ab[(kk + tig) * GS + mr + 8]);
                af[mf][2] = __float_as_uint(Ab[(kk + tig + 4) * GS + mr]);
                af[mf][3] = __float_as_uint(Ab[(kk + tig + 4) * GS + mr + 8]);
            }
            #pragma unroll
            for (int nf = 0; nf < 4; nf++) {
                int nr = n0w + nf * 8 + gid;
                bfr[nf][0] = __float_as_uint(Bb[(kk + tig) * GS + nr]);
                bfr[nf][1] = __float_as_uint(Bb[(kk + tig + 4) * GS + nr]);
            }
            #pragma unroll
            for (int mf = 0; mf < 4; mf++)
                #pragma unroll
                for (int nf = 0; nf < 4; nf++)
                    mma8(acc[mf][nf], af[mf][0], af[mf][1], af[mf][2], af[mf][3],
                         bfr[nf][0], bfr[nf][1]);
        }
        cur = (cur + 1) % 3;
    }

    float* outp = &g_xg[dir][0][0][0];
    #pragma unroll
    for (int nf = 0; nf < 4; nf++) {
        int ncol = nBase + n0w + nf * 8 + 2 * tig;
        float2 bv = *(const float2*)&bias[ncol];
        #pragma unroll
        for (int mf = 0; mf < 4; mf++) {
            int r0 = mBase + m0w + mf * 16 + gid;
            float2 v0 = make_float2(acc[mf][nf][0] + bv.x, acc[mf][nf][1] + bv.y);
            float2 v1 = make_float2(acc[mf][nf][2] + bv.x, acc[mf][nf][3] + bv.y);
            *(float2*)(outp + (size_t)r0 * NG + ncol)       = v0;
            *(float2*)(outp + (size_t)(r0 + 8) * NG + ncol) = v1;
        }
    }

    // release-arrive: this tile of xg is globally visible
    __syncthreads();
    if (tid == 0)
        asm volatile("red.release.gpu.global.add.u32 [%0], %1;"
                     :: "l"((unsigned*)&g_xgcnt[dir][tch][0]), "r"(1u) : "memory");
}

// =================================================================================
// Kernel B: persistent bidirectional LSTM recurrence — R9 VERBATIM (proven 2491)
// plus xg-chunk gating: at each 128-step chunk boundary, wait for the GEMM's 512
// tile-arrivals of that chunk (runs concurrently on the other stream).
// =================================================================================
#define US_STR 520
#define GP_STR 34
#define SMEM_REC ((2 * 32 * US_STR + 2 * 32 * GP_STR) * 4)

__global__ __launch_bounds__(REC_THREADS, 1) void lstm_rec(
    const float* __restrict__ z,
    const float* __restrict__ Uf, const float* __restrict__ Ub,
    float* __restrict__ out)
{
    extern __shared__ float sm[];
    float* Us = sm;                       // [32 local cols][US_STR] (k-permuted tf32)
    float* hs = sm + 32 * US_STR;         // [32 batches][US_STR]   (k-permuted tf32)
    float* gp = sm + 64 * US_STR;         // [2 khalf][32 batches][GP_STR] partial preacts

    const int bid = blockIdx.x;
    const int dir = bid & 1;
    const int blk = bid >> 1;             // 0..63
    const int chunk = blk >> 4;           // 0..3 (this CTA's producer chunk)
    const int u0  = blk * 8;
    const int tid = threadIdx.x;
    const int lane = tid & 31, wid = tid >> 5;
    const int gid = lane >> 2, tig = lane & 3;
    const int mhalf = wid & 1;
    const int gpair = (wid >> 1) & 1;
    const int khalf = wid >> 2;           // threads 0-127: 0, 128-255: 1
    const int g0 = gpair * 2, g1 = g0 + 1;
    const int r0 = mhalf * 16 + gid;
    const int lt = tid & 127;             // index within K-half group
    const float* __restrict__ Uw = dir ? Ub : Uf;

    const unsigned ep0 = g_chep[dir][chunk][0];

    // ---- load U slice into smem: Us[localcol][perm8(k)] (tf32), 256 threads ----
    {
        int ci = tid & 31;
        int kc = tid >> 5;
        int g  = ci >> 3, uul = ci & 7;
        const float* src = Uw + (size_t)(g * U_DIM + u0 + uul);
        float* dst = Us + ci * US_STR;
        for (int k = kc * 64; k < kc * 64 + 64; k++)
            dst[perm8(k)] = tf32f(src[(size_t)k * NG]);
    }

    // ---- init state: h0 = c0 = z; h stored k-PERMUTED + tf32-rounded ----
    float cst;
    {
        int b = tid >> 3, uu = tid & 7;
        float zv = z[b * U_DIM + u0 + uu];
        cst = zv;
        g_hbuf[dir][0][b][u0 + ((uu & 3) << 1) + (uu >> 2)] = tf32f(zv);
    }
    __syncthreads();
    if (tid == 0) ch_arrive(dir, chunk, ep0 + 1u);

    const float* hrow0 = hs + r0 * US_STR;
    const float* hrow1 = hs + (r0 + 8) * US_STR;
    const float* urow0 = Us + (g0 * 8 + gid) * US_STR;
    const float* urow1 = Us + (g1 * 8 + gid) * US_STR;
    float* gpb = gp + khalf * 32 * GP_STR;
    const float* xgbase = &g_xg[dir][0][0][0];
    const unsigned hs_s = (unsigned)__cvta_generic_to_shared(hs);
    const int eb = tid >> 3, euu = tid & 7;

    for (int s = 0; s < T_SEQ; s++) {
        const int buf = s & 1;
        const int tt  = dir ? (T_SEQ - 1 - s) : s;

        // gate on concurrent GEMM: at chunk boundaries wait for all 512 tiles
        // of xg t-chunk (tt>>7). Counters reset each replay -> compare vs 512.
        if ((s & 127) == 0) {
            if (tid == 0) {
                unsigned cur;
                do {
                    asm volatile("ld.acquire.gpu.u32 %0, [%1];"
                                 : "=r"(cur)
                                 : "l"((const unsigned*)&g_xgcnt[dir][tt >> 7][0])
                                 : "memory");
                } while (cur < 512u);
            }
            __syncthreads();
        }

        // prefetch xg for this step (hides under the h-wait spin)
        float xr[4];
        {
            const float* xp = xgbase + ((size_t)eb * T_SEQ + tt) * NG + u0 + euu;
            xr[0] = xp[0];
            xr[1] = xp[U_DIM];
            xr[2] = xp[2 * U_DIM];
            xr[3] = xp[3 * U_DIM];
        }

        // chunk-wise h: wait for each 128-k chunk's 16 producers, then stage it.
        const float* hsrcBase = &g_hbuf[dir][buf][0][0];
        #pragma unroll
        for (int q = 0; q < 2; q++) {
            const int ck = khalf * 2 + q;
            if (lt == 0) ch_wait(dir, ck, ep0, 1u + (unsigned)s);
            asm volatile("bar.sync %0, 128;" :: "r"(1 + khalf));
            const int kq = khalf * 256 + q * 128;
            #pragma unroll
            for (int j = 0; j < 8; j++) {
                int idx = j * 128 + lt;
                int b   = idx >> 5;
                int k   = kq + (idx & 31) * 4;
                const float* src = hsrcBase + b * U_DIM + k;
                unsigned dst = hs_s + (unsigned)(b * US_STR + k) * 4u;
                asm volatile("cp.async.cg.shared.global [%0], [%1], 16;" :: "r"(dst), "l"(src));
            }
            asm volatile("cp.async.commit_group;");
        }

        float c0f[4] = {0, 0, 0, 0}, c1f[4] = {0, 0, 0, 0};

        // sub-chunk 0 ready -> mma kb 0..15 of this half
        asm volatile("cp.async.wait_group 1;");
        asm volatile("bar.sync %0, 128;" :: "r"(1 + khalf));
        #pragma unroll 4
        for (int kb = 0; kb < 16; kb++) {
            int o = khalf * 256 + kb * 8 + 2 * tig;
            uint2 ar0 = *(const uint2*)(hrow0 + o);
            uint2 ar1 = *(const uint2*)(hrow1 + o);
            uint2 bu0 = *(const uint2*)(urow0 + o);
            uint2 bu1 = *(const uint2*)(urow1 + o);
            mma8(c0f, ar0.x, ar1.x, ar0.y, ar1.y, bu0.x, bu0.y);
            mma8(c1f, ar0.x, ar1.x, ar0.y, ar1.y, bu1.x, bu1.y);
        }
        // sub-chunk 1 ready -> mma kb 16..31
        asm volatile("cp.async.wait_group 0;");
        asm volatile("bar.sync %0, 128;" :: "r"(1 + khalf));
        #pragma unroll 4
        for (int kb = 16; kb < 32; kb++) {
            int o = khalf * 256 + kb * 8 + 2 * tig;
            uint2 ar0 = *(const uint2*)(hrow0 + o);
            uint2 ar1 = *(const uint2*)(hrow1 + o);
            uint2 bu0 = *(const uint2*)(urow0 + o);
            uint2 bu1 = *(const uint2*)(urow1 + o);
            mma8(c0f, ar0.x, ar1.x, ar0.y, ar1.y, bu0.x, bu0.y);
            mma8(c1f, ar0.x, ar1.x, ar0.y, ar1.y, bu1.x, bu1.y);
        }

        // publish partial preactivations
        *(float2*)&gpb[r0 * GP_STR + g0 * 8 + 2 * tig]       = make_float2(c0f[0], c0f[1]);
        *(float2*)&gpb[(r0 + 8) * GP_STR + g0 * 8 + 2 * tig] = make_float2(c0f[2], c0f[3]);
        *(float2*)&gpb[r0 * GP_STR + g1 * 8 + 2 * tig]       = make_float2(c1f[0], c1f[1]);
        *(float2*)&gpb[(r0 + 8) * GP_STR + g1 * 8 + 2 * tig] = make_float2(c1f[2], c1f[3]);
        __syncthreads();

        // epilogue: reduce K-halves + xg, gates (i,f,c,o), update, publish h FIRST
        float hv;
        {
            const float* p0 = gp + eb * GP_STR;
            const float* p1 = gp + (32 + eb) * GP_STR;
            float iv = fsigm(xr[0] + p0[euu]       + p1[euu]);
            float fv = fsigm(xr[1] + p0[8 + euu]   + p1[8 + euu]);
            float cc = ftanh(xr[2] + p0[16 + euu]  + p1[16 + euu]);
            float ov = fsigm(xr[3] + p0[24 + euu]  + p1[24 + euu]);
            cst = fv * cst + iv * cc;
            hv = ov * ftanh(cst);
            g_hbuf[dir][buf ^ 1][eb][u0 + ((euu & 3) << 1) + (euu >> 2)] = tf32f(hv);
        }
        __syncthreads();

        // arrive (release our slice of h(s+1)) BEFORE output stores
        if (tid == 0) ch_arrive(dir, chunk, ep0 + 2u + (unsigned)s);

        if (dir == 0)
            out[((size_t)eb * T_SEQ + s) * U_DIM + u0 + euu] = hv;
        else
            g_hb_out[eb][tt][u0 + euu] = hv;
    }
}

// =================================================================================
// Kernel C: out += backward outputs
// =================================================================================
__global__ void add_bwd(float* __restrict__ out)
{
    int i = blockIdx.x * blockDim.x + threadIdx.x;
    const int n4 = B_DIM * T_SEQ * U_DIM / 4;
    if (i < n4) {
        float4 a = ((float4*)out)[i];
        float4 b = ((const float4*)&g_hb_out[0][0][0])[i];
        a.x += b.x; a.y += b.y; a.z += b.z; a.w += b.w;
        ((float4*)out)[i] = a;
    }
}

// =================================================================================
extern "C" void kernel_launch(void* const* d_in, const int* in_sizes, int n_in,
                              void* d_out, int out_size)
{
    const float* x  = (const float*)d_in[0];
    const float* z  = (const float*)d_in[1];
    const float* Wf = (const float*)d_in[2];
    const float* Uf = (const float*)d_in[3];
    const float* bf = (const float*)d_in[4];
    const float* Wb = (const float*)d_in[5];
    const float* Ub = (const float*)d_in[6];
    const float* bb = (const float*)d_in[7];
    float* out = (float*)d_out;

    // one-time host resources (no device memory involved)
    static cudaStream_t s2 = nullptr;
    static cudaEvent_t evA = nullptr, evB = nullptr;
    if (s2 == nullptr) {
        cudaStreamCreateWithFlags(&s2, cudaStreamNonBlocking);
        cudaEventCreateWithFlags(&evA, cudaEventDisableTiming);
        cudaEventCreateWithFlags(&evB, cudaEventDisableTiming);
        cudaFuncSetAttribute(gemm_xg, cudaFuncAttributeMaxDynamicSharedMemorySize, GSMEM);
        cudaFuncSetAttribute(lstm_rec, cudaFuncAttributeMaxDynamicSharedMemorySize, SMEM_REC);
    }

    // pre-passes + flag reset (main stream)
    cvt_xT<<<dim3(D_DIM / 32, M_TOT / 32), dim3(32, 8)>>>(x);
    {
        int total4 = 2 * D_DIM * NG / 4;
        cvt_W<<<(total4 + 255) / 256, 256>>>(Wf, Wb);
    }
    reset_xg<<<1, 32>>>();

    // fork: GEMM (priority-ordered) on s2, recurrence on main stream — parallel
    cudaEventRecord(evA, 0);
    cudaStreamWaitEvent(s2, evA, 0);
    gemm_xg<<<4096, 256, GSMEM, s2>>>(bf, bb);
    cudaEventRecord(evB, s2);

    lstm_rec<<<2 * NCTA_DIR, REC_THREADS, SMEM_REC>>>(z, Uf, Ub, out);

    // join, then merge backward outputs
    cudaStreamWaitEvent(0, evB, 0);
    add_bwd<<<(B_DIM * T_SEQ * U_DIM / 4 + 255) / 256, 256>>>(out);
}

// round 16
// speedup vs baseline: 1.0396x; 1.0396x over previous
#include <cuda_runtime.h>
#include <math.h>
#include <stdint.h>

#define B_DIM 32
#define T_SEQ 512
#define D_DIM 512
#define U_DIM 512
#define NG    2048                 // 4*U
#define M_TOT (B_DIM * T_SEQ)     // 16384

// ---------------- scratch (static device memory; no allocations) ----------------
__device__ float g_xg[2][B_DIM][T_SEQ][NG];        // input projections, both dirs (256 MB)
__device__ float g_hbuf[2][2][B_DIM][U_DIM];       // h double buffers (k-PERMUTED, tf32-rounded)
__device__ float g_xT[D_DIM][M_TOT];               // tf32-rounded x, TRANSPOSED [k][m] (32 MB)
__device__ float g_Wc[2][D_DIM][NG];               // tf32-rounded W copies [dir][k][n] (16 MB)

// h-chunk barrier (R9, proven): chunk c = producer CTAs blk 16c..16c+15 = k-range
// [128c,128c+128). Padded lines, monotonic across graph replays.
__device__ unsigned g_chcnt[2][4][32];             // [dir][chunk][pad] arrival counters
__device__ volatile unsigned g_chep[2][4][32];     // [dir][chunk][pad] chunk epochs

#define NCTA_DIR    64
#define REC_THREADS 256

// ---------------- tf32 helpers ----------------
__device__ __forceinline__ unsigned f2tf32(float f)
{
    unsigned r;
    asm("cvt.rna.tf32.f32 %0, %1;" : "=r"(r) : "f"(f));
    return r;
}
__device__ __forceinline__ float tf32f(float f) { return __uint_as_float(f2tf32(f)); }

// D += A@B, m16n8k8, A row-major, B col-major, tf32 in / fp32 accum
__device__ __forceinline__ void mma8(float* c,
                                     unsigned a0, unsigned a1, unsigned a2, unsigned a3,
                                     unsigned b0, unsigned b1)
{
    asm("mma.sync.aligned.m16n8k8.row.col.f32.tf32.tf32.f32 "
        "{%0,%1,%2,%3},{%4,%5,%6,%7},{%8,%9},{%0,%1,%2,%3};"
        : "+f"(c[0]), "+f"(c[1]), "+f"(c[2]), "+f"(c[3])
        : "r"(a0), "r"(a1), "r"(a2), "r"(a3), "r"(b0), "r"(b1));
}

// k-permutation within each 8-block: (pi(k),pi(k)+1) consecutive = (k, k+4)
__device__ __forceinline__ int perm8(int k)
{
    return (k & ~7) | ((k & 3) << 1) | ((k & 7) >> 2);
}

// ---------------- fast transcendentals (MUFU-based, saturation-safe) ----------------
__device__ __forceinline__ float fsigm(float x)
{
    return __fdividef(1.0f, 1.0f + __expf(-x));
}
__device__ __forceinline__ float ftanh(float x)
{
    return 1.0f - __fdividef(2.0f, 1.0f + __expf(2.0f * x));
}

// ---------------- release/acquire barrier primitives (no full MEMBAR) ----------------
__device__ __forceinline__ void ch_arrive(int dir, int chunk, unsigned ep_next)
{
    unsigned v;
    asm volatile("atom.add.release.gpu.u32 %0, [%1], %2;"
                 : "=r"(v)
                 : "l"((unsigned*)&g_chcnt[dir][chunk][0]), "r"(1u)
                 : "memory");
    if ((v & 15u) == 15u)
        asm volatile("st.release.gpu.u32 [%0], %1;"
                     :: "l"((unsigned*)&g_chep[dir][chunk][0]), "r"(ep_next)
                     : "memory");
}

__device__ __forceinline__ void ch_wait(int dir, int ck, unsigned ep0, unsigned need)
{
    unsigned cur;
    do {
        asm volatile("ld.acquire.gpu.u32 %0, [%1];"
                     : "=r"(cur)
                     : "l"((const unsigned*)&g_chep[dir][ck][0])
                     : "memory");
    } while (cur - ep0 < need);
}

// fire-and-forget global add (no return: cheaper than ATOM, order-free merge)
__device__ __forceinline__ void red_add(float* addr, float v)
{
    asm volatile("red.global.add.f32 [%0], %1;" :: "l"(addr), "f"(v) : "memory");
}

// =================================================================================
// Pre-pass 1: x[m][k] -> g_xT[k][m], tf32-rounded (smem tile transpose)
// =================================================================================
__global__ void cvt_xT(const float* __restrict__ X)
{
    __shared__ float t[32][33];
    const int kb = blockIdx.x * 32;
    const int mb = blockIdx.y * 32;
    const int tx = threadIdx.x, ty = threadIdx.y;
    #pragma unroll
    for (int i = ty; i < 32; i += 8)
        t[i][tx] = X[(size_t)(mb + i) * D_DIM + kb + tx];
    __syncthreads();
    #pragma unroll
    for (int i = ty; i < 32; i += 8)
        g_xT[kb + i][mb + tx] = tf32f(t[tx][i]);
}

// =================================================================================
// Pre-pass 2: W[dir][k][n] tf32-rounded straight copy
// =================================================================================
__global__ void cvt_W(const float* __restrict__ Wf, const float* __restrict__ Wb)
{
    const int n4 = D_DIM * NG / 4;
    int i = blockIdx.x * blockDim.x + threadIdx.x;
    if (i < 2 * n4) {
        int dir = i >= n4;
        int j = dir ? i - n4 : i;
        float4 v = ((const float4*)(dir ? Wb : Wf))[j];
        v.x = tf32f(v.x); v.y = tf32f(v.y); v.z = tf32f(v.z); v.w = tf32f(v.w);
        ((float4*)&g_Wc[dir][0][0])[j] = v;
    }
}

// =================================================================================
// Kernel A: xg GEMM — R14's measured-fastest variant (386us, tensor 59%):
// 1-D grid with [prio-group, dir, batch, n-tile] decode, cp.async 3-stage ring,
// 128x128 tile, BK=16. Serial launch (no arrival counters, no second stream).
// =================================================================================
#define GS 136
#define GSMEM (3 * 16 * GS * 4 * 2)                // 52,224 B

__global__ __launch_bounds__(256, 2) void gemm_xg(
    const float* __restrict__ bf, const float* __restrict__ bb)
{
    extern __shared__ float gsm[];
    float* As = gsm;                   // [3][16][GS]
    float* Bs = gsm + 3 * 16 * GS;     // [3][16][GS]

    const int bidx = blockIdx.x;               // 0..4095
    const int pg   = bidx >> 10;               // 0..3
    const int r    = bidx & 1023;
    const int dir  = r >> 9;
    const int q    = r & 511;
    const int bb_i = q & 31;                   // batch
    const int nt   = q >> 5;                   // 0..15
    const int tch  = dir ? (3 - pg) : pg;      // t-chunk
    const int mBase = bb_i * T_SEQ + tch * 128;
    const int nBase = nt * 128;

    const float* __restrict__ bias = dir ? bb : bf;

    const int tid   = threadIdx.x;
    const int lane  = tid & 31, wid = tid >> 5;
    const int gid   = lane >> 2, tig = lane & 3;
    const int m0w   = (wid & 1) * 64;
    const int n0w   = (wid >> 1) * 32;

    const unsigned As_s = (unsigned)__cvta_generic_to_shared(As);
    const unsigned Bs_s = (unsigned)__cvta_generic_to_shared(Bs);
    const float* Wd = &g_Wc[dir][0][0];

    auto stage = [&](int buf, int kt) {
        #pragma unroll
        for (int j = 0; j < 2; j++) {
            int ca  = tid + j * 256;
            int row = ca >> 5;
            int c16 = (ca & 31) * 4;
            const float* srcA = &g_xT[kt + row][mBase + c16];
            const float* srcB = Wd + (size_t)(kt + row) * NG + nBase + c16;
            unsigned dA = As_s + (unsigned)((buf * 16 + row) * GS + c16) * 4u;
            unsigned dB = Bs_s + (unsigned)((buf * 16 + row) * GS + c16) * 4u;
            asm volatile("cp.async.cg.shared.global [%0], [%1], 16;" :: "r"(dA), "l"(srcA));
            asm volatile("cp.async.cg.shared.global [%0], [%1], 16;" :: "r"(dB), "l"(srcB));
        }
        asm volatile("cp.async.commit_group;");
    };

    float acc[4][4][4];
    #pragma unroll
    for (int i = 0; i < 4; i++)
        #pragma unroll
        for (int j = 0; j < 4; j++)
            #pragma unroll
            for (int qq = 0; qq < 4; qq++) acc[i][j][qq] = 0.0f;

    stage(0, 0);
    stage(1, 16);

    int cur = 0;
    for (int kt = 0; kt < D_DIM; kt += 16) {
        if (kt + 32 < D_DIM) asm volatile("cp.async.wait_group 1;");
        else                 asm volatile("cp.async.wait_group 0;");
        __syncthreads();
        if (kt + 32 < D_DIM) stage((cur + 2) % 3, kt + 32);

        const float* Ab = As + cur * 16 * GS;
        const float* Bb = Bs + cur * 16 * GS;
        #pragma unroll
        for (int kk = 0; kk < 16; kk += 8) {
            unsigned af[4][4], bfr[4][2];
            #pragma unroll
            for (int mf = 0; mf < 4; mf++) {
                int mr = m0w + mf * 16 + gid;
                af[mf][0] = __float_as_uint(Ab[(kk + tig) * GS + mr]);
                af[mf][1] = __float_as_uint(Ab[(kk + tig) * GS + mr + 8]);
                af[mf][2] = __float_as_uint(Ab[(kk + tig + 4) * GS + mr]);
                af[mf][3] = __float_as_uint(Ab[(kk + tig + 4) * GS + mr + 8]);
            }
            #pragma unroll
            for (int nf = 0; nf < 4; nf++) {
                int nr = n0w + nf * 8 + gid;
                bfr[nf][0] = __float_as_uint(Bb[(kk + tig) * GS + nr]);
                bfr[nf][1] = __float_as_uint(Bb[(kk + tig + 4) * GS + nr]);
            }
            #pragma unroll
            for (int mf = 0; mf < 4; mf++)
                #pragma unroll
                for (int nf = 0; nf < 4; nf++)
                    mma8(acc[mf][nf], af[mf][0], af[mf][1], af[mf][2], af[mf][3],
                         bfr[nf][0], bfr[nf][1]);
        }
        cur = (cur + 1) % 3;
    }

    float* outp = &g_xg[dir][0][0][0];
    #pragma unroll
    for (int nf = 0; nf < 4; nf++) {
        int ncol = nBase + n0w + nf * 8 + 2 * tig;
        float2 bv = *(const float2*)&bias[ncol];
        #pragma unroll
        for (int mf = 0; mf < 4; mf++) {
            int r0 = mBase + m0w + mf * 16 + gid;
            float2 v0 = make_float2(acc[mf][nf][0] + bv.x, acc[mf][nf][1] + bv.y);
            float2 v1 = make_float2(acc[mf][nf][2] + bv.x, acc[mf][nf][3] + bv.y);
            *(float2*)(outp + (size_t)r0 * NG + ncol)       = v0;
            *(float2*)(outp + (size_t)(r0 + 8) * NG + ncol) = v1;
        }
    }
}

// =================================================================================
// Kernel B: persistent bidirectional LSTM recurrence — R9 VERBATIM (proven 2491),
// except outputs: BOTH directions red.add into zeroed `out` (order-free merge,
// bit-identical to fwd+bwd; deletes add_bwd kernel and g_hb_out traffic).
// =================================================================================
#define US_STR 520
#define GP_STR 34
#define SMEM_REC ((2 * 32 * US_STR + 2 * 32 * GP_STR) * 4)

__global__ __launch_bounds__(REC_THREADS, 1) void lstm_rec(
    const float* __restrict__ z,
    const float* __restrict__ Uf, const float* __restrict__ Ub,
    float* __restrict__ out)
{
    extern __shared__ float sm[];
    float* Us = sm;                       // [32 local cols][US_STR] (k-permuted tf32)
    float* hs = sm + 32 * US_STR;         // [32 batches][US_STR]   (k-permuted tf32)
    float* gp = sm + 64 * US_STR;         // [2 khalf][32 batches][GP_STR] partial preacts

    const int bid = blockIdx.x;
    const int dir = bid & 1;
    const int blk = bid >> 1;             // 0..63
    const int chunk = blk >> 4;           // 0..3 (this CTA's producer chunk)
    const int u0  = blk * 8;
    const int tid = threadIdx.x;
    const int lane = tid & 31, wid = tid >> 5;
    const int gid = lane >> 2, tig = lane & 3;
    const int mhalf = wid & 1;
    const int gpair = (wid >> 1) & 1;
    const int khalf = wid >> 2;           // threads 0-127: 0, 128-255: 1
    const int g0 = gpair * 2, g1 = g0 + 1;
    const int r0 = mhalf * 16 + gid;
    const int lt = tid & 127;             // index within K-half group
    const float* __restrict__ Uw = dir ? Ub : Uf;

    const unsigned ep0 = g_chep[dir][chunk][0];

    // ---- load U slice into smem: Us[localcol][perm8(k)] (tf32), 256 threads ----
    {
        int ci = tid & 31;
        int kc = tid >> 5;
        int g  = ci >> 3, uul = ci & 7;
        const float* src = Uw + (size_t)(g * U_DIM + u0 + uul);
        float* dst = Us + ci * US_STR;
        for (int k = kc * 64; k < kc * 64 + 64; k++)
            dst[perm8(k)] = tf32f(src[(size_t)k * NG]);
    }

    // ---- init state: h0 = c0 = z; h stored k-PERMUTED + tf32-rounded ----
    float cst;
    {
        int b = tid >> 3, uu = tid & 7;
        float zv = z[b * U_DIM + u0 + uu];
        cst = zv;
        g_hbuf[dir][0][b][u0 + ((uu & 3) << 1) + (uu >> 2)] = tf32f(zv);
    }
    __syncthreads();
    if (tid == 0) ch_arrive(dir, chunk, ep0 + 1u);

    const float* hrow0 = hs + r0 * US_STR;
    const float* hrow1 = hs + (r0 + 8) * US_STR;
    const float* urow0 = Us + (g0 * 8 + gid) * US_STR;
    const float* urow1 = Us + (g1 * 8 + gid) * US_STR;
    float* gpb = gp + khalf * 32 * GP_STR;
    const float* xgbase = &g_xg[dir][0][0][0];
    const unsigned hs_s = (unsigned)__cvta_generic_to_shared(hs);
    const int eb = tid >> 3, euu = tid & 7;

    for (int s = 0; s < T_SEQ; s++) {
        const int buf = s & 1;
        const int tt  = dir ? (T_SEQ - 1 - s) : s;

        // prefetch xg for this step (hides under the h-wait spin)
        float xr[4];
        {
            const float* xp = xgbase + ((size_t)eb * T_SEQ + tt) * NG + u0 + euu;
            xr[0] = xp[0];
            xr[1] = xp[U_DIM];
            xr[2] = xp[2 * U_DIM];
            xr[3] = xp[3 * U_DIM];
        }

        // chunk-wise h: wait for each 128-k chunk's 16 producers, then stage it.
        const float* hsrcBase = &g_hbuf[dir][buf][0][0];
        #pragma unroll
        for (int q = 0; q < 2; q++) {
            const int ck = khalf * 2 + q;
            if (lt == 0) ch_wait(dir, ck, ep0, 1u + (unsigned)s);
            asm volatile("bar.sync %0, 128;" :: "r"(1 + khalf));
            const int kq = khalf * 256 + q * 128;
            #pragma unroll
            for (int j = 0; j < 8; j++) {
                int idx = j * 128 + lt;
                int b   = idx >> 5;
                int k   = kq + (idx & 31) * 4;
                const float* src = hsrcBase + b * U_DIM + k;
                unsigned dst = hs_s + (unsigned)(b * US_STR + k) * 4u;
                asm volatile("cp.async.cg.shared.global [%0], [%1], 16;" :: "r"(dst), "l"(src));
            }
            asm volatile("cp.async.commit_group;");
        }

        float c0f[4] = {0, 0, 0, 0}, c1f[4] = {0, 0, 0, 0};

        // sub-chunk 0 ready -> mma kb 0..15 of this half
        asm volatile("cp.async.wait_group 1;");
        asm volatile("bar.sync %0, 128;" :: "r"(1 + khalf));
        #pragma unroll 4
        for (int kb = 0; kb < 16; kb++) {
            int o = khalf * 256 + kb * 8 + 2 * tig;
            uint2 ar0 = *(const uint2*)(hrow0 + o);
            uint2 ar1 = *(const uint2*)(hrow1 + o);
            uint2 bu0 = *(const uint2*)(urow0 + o);
            uint2 bu1 = *(const uint2*)(urow1 + o);
            mma8(c0f, ar0.x, ar1.x, ar0.y, ar1.y, bu0.x, bu0.y);
            mma8(c1f, ar0.x, ar1.x, ar0.y, ar1.y, bu1.x, bu1.y);
        }
        // sub-chunk 1 ready -> mma kb 16..31
        asm volatile("cp.async.wait_group 0;");
        asm volatile("bar.sync %0, 128;" :: "r"(1 + khalf));
        #pragma unroll 4
        for (int kb = 16; kb < 32; kb++) {
            int o = khalf * 256 + kb * 8 + 2 * tig;
            uint2 ar0 = *(const uint2*)(hrow0 + o);
            uint2 ar1 = *(const uint2*)(hrow1 + o);
            uint2 bu0 = *(const uint2*)(urow0 + o);
            uint2 bu1 = *(const uint2*)(urow1 + o);
            mma8(c0f, ar0.x, ar1.x, ar0.y, ar1.y, bu0.x, bu0.y);
            mma8(c1f, ar0.x, ar1.x, ar0.y, ar1.y, bu1.x, bu1.y);
        }

        // publish partial preactivations
        *(float2*)&gpb[r0 * GP_STR + g0 * 8 + 2 * tig]       = make_float2(c0f[0], c0f[1]);
        *(float2*)&gpb[(r0 + 8) * GP_STR + g0 * 8 + 2 * tig] = make_float2(c0f[2], c0f[3]);
        *(float2*)&gpb[r0 * GP_STR + g1 * 8 + 2 * tig]       = make_float2(c1f[0], c1f[1]);
        *(float2*)&gpb[(r0 + 8) * GP_STR + g1 * 8 + 2 * tig] = make_float2(c1f[2], c1f[3]);
        __syncthreads();

        // epilogue: reduce K-halves + xg, gates (i,f,c,o), update, publish h FIRST
        float hv;
        {
            const float* p0 = gp + eb * GP_STR;
            const float* p1 = gp + (32 + eb) * GP_STR;
            float iv = fsigm(xr[0] + p0[euu]       + p1[euu]);
            float fv = fsigm(xr[1] + p0[8 + euu]   + p1[8 + euu]);
            float cc = ftanh(xr[2] + p0[16 + euu]  + p1[16 + euu]);
            float ov = fsigm(xr[3] + p0[24 + euu]  + p1[24 + euu]);
            cst = fv * cst + iv * cc;
            hv = ov * ftanh(cst);
            g_hbuf[dir][buf ^ 1][eb][u0 + ((euu & 3) << 1) + (euu >> 2)] = tf32f(hv);
        }
        __syncthreads();

        // arrive (release our slice of h(s+1)) BEFORE output stores
        if (tid == 0) ch_arrive(dir, chunk, ep0 + 2u + (unsigned)s);

        // merge into zero-initialized out (order-free across directions)
        red_add(out + ((size_t)eb * T_SEQ + tt) * U_DIM + u0 + euu, hv);
    }
}

// =================================================================================
extern "C" void kernel_launch(void* const* d_in, const int* in_sizes, int n_in,
                              void* d_out, int out_size)
{
    const float* x  = (const float*)d_in[0];
    const float* z  = (const float*)d_in[1];
    const float* Wf = (const float*)d_in[2];
    const float* Uf = (const float*)d_in[3];
    const float* bf = (const float*)d_in[4];
    const float* Wb = (const float*)d_in[5];
    const float* Ub = (const float*)d_in[6];
    const float* bb = (const float*)d_in[7];
    float* out = (float*)d_out;

    cudaFuncSetAttribute(gemm_xg, cudaFuncAttributeMaxDynamicSharedMemorySize, GSMEM);
    cudaFuncSetAttribute(lstm_rec, cudaFuncAttributeMaxDynamicSharedMemorySize, SMEM_REC);

    // pre-passes: tf32-rounded x (transposed) + W copies; zero the output for RED merge
    cvt_xT<<<dim3(D_DIM / 32, M_TOT / 32), dim3(32, 8)>>>(x);
    {
        int total4 = 2 * D_DIM * NG / 4;
        cvt_W<<<(total4 + 255) / 256, 256>>>(Wf, Wb);
    }
    cudaMemsetAsync(out, 0, (size_t)out_size * sizeof(float), 0);

    gemm_xg<<<4096, 256, GSMEM>>>(bf, bb);
    lstm_rec<<<2 * NCTA_DIR, REC_THREADS, SMEM_REC>>>(z, Uf, Ub, out);
}

// round 17
// speedup vs baseline: 1.0575x; 1.0173x over previous
#include <cuda_runtime.h>
#include <math.h>
#include <stdint.h>

#define B_DIM 32
#define T_SEQ 512
#define D_DIM 512
#define U_DIM 512
#define NG    2048                 // 4*U
#define M_TOT (B_DIM * T_SEQ)     // 16384

// ---------------- scratch (static device memory; no allocations) ----------------
__device__ float g_xg[2][B_DIM][T_SEQ][NG];        // input projections, both dirs (256 MB)
__device__ float g_hbuf[2][2][B_DIM][U_DIM];       // h double buffers (k-PERMUTED, tf32-rounded)
__device__ float g_xT[D_DIM][M_TOT];               // tf32-rounded x, TRANSPOSED [k][m] (32 MB)
__device__ float g_Wc[2][D_DIM][NG];               // tf32-rounded W copies [dir][k][n] (16 MB)

// h-chunk barrier (R9, proven): chunk c = producer CTAs blk 16c..16c+15 = k-range
// [128c,128c+128). Padded lines, monotonic across graph replays.
__device__ unsigned g_chcnt[2][4][32];             // [dir][chunk][pad] arrival counters
__device__ volatile unsigned g_chep[2][4][32];     // [dir][chunk][pad] chunk epochs

#define NCTA_DIR    64
#define REC_THREADS 512

// ---------------- tf32 helpers ----------------
__device__ __forceinline__ unsigned f2tf32(float f)
{
    unsigned r;
    asm("cvt.rna.tf32.f32 %0, %1;" : "=r"(r) : "f"(f));
    return r;
}
__device__ __forceinline__ float tf32f(float f) { return __uint_as_float(f2tf32(f)); }

// D += A@B, m16n8k8, A row-major, B col-major, tf32 in / fp32 accum
__device__ __forceinline__ void mma8(float* c,
                                     unsigned a0, unsigned a1, unsigned a2, unsigned a3,
                                     unsigned b0, unsigned b1)
{
    asm("mma.sync.aligned.m16n8k8.row.col.f32.tf32.tf32.f32 "
        "{%0,%1,%2,%3},{%4,%5,%6,%7},{%8,%9},{%0,%1,%2,%3};"
        : "+f"(c[0]), "+f"(c[1]), "+f"(c[2]), "+f"(c[3])
        : "r"(a0), "r"(a1), "r"(a2), "r"(a3), "r"(b0), "r"(b1));
}

// k-permutation within each 8-block: (pi(k),pi(k)+1) consecutive = (k, k+4)
__device__ __forceinline__ int perm8(int k)
{
    return (k & ~7) | ((k & 3) << 1) | ((k & 7) >> 2);
}

// ---------------- fast transcendentals (MUFU-based, saturation-safe) ----------------
__device__ __forceinline__ float fsigm(float x)
{
    return __fdividef(1.0f, 1.0f + __expf(-x));
}
__device__ __forceinline__ float ftanh(float x)
{
    return 1.0f - __fdividef(2.0f, 1.0f + __expf(2.0f * x));
}

// ---------------- release/acquire barrier primitives (no full MEMBAR) ----------------
__device__ __forceinline__ void ch_arrive(int dir, int chunk, unsigned ep_next)
{
    unsigned v;
    asm volatile("atom.add.release.gpu.u32 %0, [%1], %2;"
                 : "=r"(v)
                 : "l"((unsigned*)&g_chcnt[dir][chunk][0]), "r"(1u)
                 : "memory");
    if ((v & 15u) == 15u)
        asm volatile("st.release.gpu.u32 [%0], %1;"
                     :: "l"((unsigned*)&g_chep[dir][chunk][0]), "r"(ep_next)
                     : "memory");
}

__device__ __forceinline__ void ch_wait(int dir, int ck, unsigned ep0, unsigned need)
{
    unsigned cur;
    do {
        asm volatile("ld.acquire.gpu.u32 %0, [%1];"
                     : "=r"(cur)
                     : "l"((const unsigned*)&g_chep[dir][ck][0])
                     : "memory");
    } while (cur - ep0 < need);
}

// fire-and-forget global add (no return; order-free merge into zeroed out)
__device__ __forceinline__ void red_add(float* addr, float v)
{
    asm volatile("red.global.add.f32 [%0], %1;" :: "l"(addr), "f"(v) : "memory");
}

// =================================================================================
// Pre-pass 1: x[m][k] -> g_xT[k][m], tf32-rounded (smem tile transpose)
// =================================================================================
__global__ void cvt_xT(const float* __restrict__ X)
{
    __shared__ float t[32][33];
    const int kb = blockIdx.x * 32;
    const int mb = blockIdx.y * 32;
    const int tx = threadIdx.x, ty = threadIdx.y;
    #pragma unroll
    for (int i = ty; i < 32; i += 8)
        t[i][tx] = X[(size_t)(mb + i) * D_DIM + kb + tx];
    __syncthreads();
    #pragma unroll
    for (int i = ty; i < 32; i += 8)
        g_xT[kb + i][mb + tx] = tf32f(t[tx][i]);
}

// =================================================================================
// Pre-pass 2: W[dir][k][n] tf32-rounded straight copy
// =================================================================================
__global__ void cvt_W(const float* __restrict__ Wf, const float* __restrict__ Wb)
{
    const int n4 = D_DIM * NG / 4;
    int i = blockIdx.x * blockDim.x + threadIdx.x;
    if (i < 2 * n4) {
        int dir = i >= n4;
        int j = dir ? i - n4 : i;
        float4 v = ((const float4*)(dir ? Wb : Wf))[j];
        v.x = tf32f(v.x); v.y = tf32f(v.y); v.z = tf32f(v.z); v.w = tf32f(v.w);
        ((float4*)&g_Wc[dir][0][0])[j] = v;
    }
}

// =================================================================================
// Kernel A: xg GEMM — R14/R15's measured-fastest variant (386us, tensor 59%).
// =================================================================================
#define GS 136
#define GSMEM (3 * 16 * GS * 4 * 2)                // 52,224 B

__global__ __launch_bounds__(256, 2) void gemm_xg(
    const float* __restrict__ bf, const float* __restrict__ bb)
{
    extern __shared__ float gsm[];
    float* As = gsm;                   // [3][16][GS]
    float* Bs = gsm + 3 * 16 * GS;     // [3][16][GS]

    const int bidx = blockIdx.x;               // 0..4095
    const int pg   = bidx >> 10;               // 0..3
    const int r    = bidx & 1023;
    const int dir  = r >> 9;
    const int q    = r & 511;
    const int bb_i = q & 31;                   // batch
    const int nt   = q >> 5;                   // 0..15
    const int tch  = dir ? (3 - pg) : pg;      // t-chunk
    const int mBase = bb_i * T_SEQ + tch * 128;
    const int nBase = nt * 128;

    const float* __restrict__ bias = dir ? bb : bf;

    const int tid   = threadIdx.x;
    const int lane  = tid & 31, wid = tid >> 5;
    const int gid   = lane >> 2, tig = lane & 3;
    const int m0w   = (wid & 1) * 64;
    const int n0w   = (wid >> 1) * 32;

    const unsigned As_s = (unsigned)__cvta_generic_to_shared(As);
    const unsigned Bs_s = (unsigned)__cvta_generic_to_shared(Bs);
    const float* Wd = &g_Wc[dir][0][0];

    auto stage = [&](int buf, int kt) {
        #pragma unroll
        for (int j = 0; j < 2; j++) {
            int ca  = tid + j * 256;
            int row = ca >> 5;
            int c16 = (ca & 31) * 4;
            const float* srcA = &g_xT[kt + row][mBase + c16];
            const float* srcB = Wd + (size_t)(kt + row) * NG + nBase + c16;
            unsigned dA = As_s + (unsigned)((buf * 16 + row) * GS + c16) * 4u;
            unsigned dB = Bs_s + (unsigned)((buf * 16 + row) * GS + c16) * 4u;
            asm volatile("cp.async.cg.shared.global [%0], [%1], 16;" :: "r"(dA), "l"(srcA));
            asm volatile("cp.async.cg.shared.global [%0], [%1], 16;" :: "r"(dB), "l"(srcB));
        }
        asm volatile("cp.async.commit_group;");
    };

    float acc[4][4][4];
    #pragma unroll
    for (int i = 0; i < 4; i++)
        #pragma unroll
        for (int j = 0; j < 4; j++)
            #pragma unroll
            for (int qq = 0; qq < 4; qq++) acc[i][j][qq] = 0.0f;

    stage(0, 0);
    stage(1, 16);

    int cur = 0;
    for (int kt = 0; kt < D_DIM; kt += 16) {
        if (kt + 32 < D_DIM) asm volatile("cp.async.wait_group 1;");
        else                 asm volatile("cp.async.wait_group 0;");
        __syncthreads();
        if (kt + 32 < D_DIM) stage((cur + 2) % 3, kt + 32);

        const float* Ab = As + cur * 16 * GS;
        const float* Bb = Bs + cur * 16 * GS;
        #pragma unroll
        for (int kk = 0; kk < 16; kk += 8) {
            unsigned af[4][4], bfr[4][2];
            #pragma unroll
            for (int mf = 0; mf < 4; mf++) {
                int mr = m0w + mf * 16 + gid;
                af[mf][0] = __float_as_uint(Ab[(kk + tig) * GS + mr]);
                af[mf][1] = __float_as_uint(Ab[(kk + tig) * GS + mr + 8]);
                af[mf][2] = __float_as_uint(Ab[(kk + tig + 4) * GS + mr]);
                af[mf][3] = __float_as_uint(Ab[(kk + tig + 4) * GS + mr + 8]);
            }
            #pragma unroll
            for (int nf = 0; nf < 4; nf++) {
                int nr = n0w + nf * 8 + gid;
                bfr[nf][0] = __float_as_uint(Bb[(kk + tig) * GS + nr]);
                bfr[nf][1] = __float_as_uint(Bb[(kk + tig + 4) * GS + nr]);
            }
            #pragma unroll
            for (int mf = 0; mf < 4; mf++)
                #pragma unroll
                for (int nf = 0; nf < 4; nf++)
                    mma8(acc[mf][nf], af[mf][0], af[mf][1], af[mf][2], af[mf][3],
                         bfr[nf][0], bfr[nf][1]);
        }
        cur = (cur + 1) % 3;
    }

    float* outp = &g_xg[dir][0][0][0];
    #pragma unroll
    for (int nf = 0; nf < 4; nf++) {
        int ncol = nBase + n0w + nf * 8 + 2 * tig;
        float2 bv = *(const float2*)&bias[ncol];
        #pragma unroll
        for (int mf = 0; mf < 4; mf++) {
            int r0 = mBase + m0w + mf * 16 + gid;
            float2 v0 = make_float2(acc[mf][nf][0] + bv.x, acc[mf][nf][1] + bv.y);
            float2 v1 = make_float2(acc[mf][nf][2] + bv.x, acc[mf][nf][3] + bv.y);
            *(float2*)(outp + (size_t)r0 * NG + ncol)       = v0;
            *(float2*)(outp + (size_t)(r0 + 8) * NG + ncol) = v1;
        }
    }
}

// =================================================================================
// Kernel B: persistent bidirectional LSTM recurrence — tf32 tensor cores.
// 128 CTAs (64/dir), NOW 512 threads (16 warps), CTA owns 8 units. 4-way split-K:
// quarter q (warps 4q..4q+3, threads 128q..128q+127) owns k-range [128q,128q+128)
// and its 1:1 producer chunk — own poll, own 8-cp.async stage, own 16-kb mma.
// Four fully independent pipelines per CTA; partials (4) reduced in epilogue.
// =================================================================================
#define US_STR 520
#define GP_STR 34
#define SMEM_REC ((2 * 32 * US_STR + 4 * 32 * GP_STR) * 4)   // 150,528 B

__global__ __launch_bounds__(REC_THREADS, 1) void lstm_rec(
    const float* __restrict__ z,
    const float* __restrict__ Uf, const float* __restrict__ Ub,
    float* __restrict__ out)
{
    extern __shared__ float sm[];
    float* Us = sm;                       // [32 local cols][US_STR] (k-permuted tf32)
    float* hs = sm + 32 * US_STR;         // [32 batches][US_STR]   (k-permuted tf32)
    float* gp = sm + 64 * US_STR;         // [4 quarter][32 batches][GP_STR] partials

    const int bid = blockIdx.x;
    const int dir = bid & 1;
    const int blk = bid >> 1;             // 0..63
    const int chunk = blk >> 4;           // 0..3 (this CTA's producer chunk)
    const int u0  = blk * 8;
    const int tid = threadIdx.x;
    const int lane = tid & 31, wid = tid >> 5;
    const int gid = lane >> 2, tig = lane & 3;
    const int quarter = wid >> 2;         // 0..3: k-quarter group (128 threads)
    const int wq    = wid & 3;            // warp role within quarter
    const int gpair = wq & 1;
    const int mhalf = wq >> 1;
    const int g0 = gpair * 2, g1 = g0 + 1;
    const int r0 = mhalf * 16 + gid;
    const int lt = tid & 127;             // index within quarter group
    const float* __restrict__ Uw = dir ? Ub : Uf;

    const unsigned ep0 = g_chep[dir][chunk][0];

    // ---- load U slice into smem: Us[localcol][perm8(k)] (tf32), 512 threads ----
    {
        int ci = tid & 31;                // local col: gate(ci>>3) x unit(ci&7)
        int kc = tid >> 5;                // k chunk (0..15), 32 k each
        int g  = ci >> 3, uul = ci & 7;
        const float* src = Uw + (size_t)(g * U_DIM + u0 + uul);
        float* dst = Us + ci * US_STR;
        for (int k = kc * 32; k < kc * 32 + 32; k++)
            dst[perm8(k)] = tf32f(src[(size_t)k * NG]);
    }

    // ---- init state: h0 = c0 = z; h stored k-PERMUTED + tf32-rounded ----
    float cst = 0.0f;
    if (tid < 256) {
        int b = tid >> 3, uu = tid & 7;
        float zv = z[b * U_DIM + u0 + uu];
        cst = zv;
        g_hbuf[dir][0][b][u0 + ((uu & 3) << 1) + (uu >> 2)] = tf32f(zv);
    }
    __syncthreads();
    if (tid == 0) ch_arrive(dir, chunk, ep0 + 1u);

    const float* hrow0 = hs + r0 * US_STR;
    const float* hrow1 = hs + (r0 + 8) * US_STR;
    const float* urow0 = Us + (g0 * 8 + gid) * US_STR;
    const float* urow1 = Us + (g1 * 8 + gid) * US_STR;
    float* gpq = gp + quarter * 32 * GP_STR;
    const float* xgbase = &g_xg[dir][0][0][0];
    const unsigned hs_s = (unsigned)__cvta_generic_to_shared(hs);
    const int eb = tid >> 3, euu = tid & 7;           // epilogue (batch, unit), tid<256

    for (int s = 0; s < T_SEQ; s++) {
        const int buf = s & 1;
        const int tt  = dir ? (T_SEQ - 1 - s) : s;

        // prefetch xg for this step (tid<256; hides under the chunk poll)
        float xr[4] = {0, 0, 0, 0};
        if (tid < 256) {
            const float* xp = xgbase + ((size_t)eb * T_SEQ + tt) * NG + u0 + euu;
            xr[0] = xp[0];
            xr[1] = xp[U_DIM];
            xr[2] = xp[2 * U_DIM];
            xr[3] = xp[3 * U_DIM];
        }

        // quarter-independent pipeline: poll own chunk -> stage 16 KB -> mma 16 kb
        const float* hsrcBase = &g_hbuf[dir][buf][0][0];
        if (lt == 0) ch_wait(dir, quarter, ep0, 1u + (unsigned)s);
        asm volatile("bar.sync %0, 128;" :: "r"(1 + quarter));
        {
            const int kq = quarter * 128;
            #pragma unroll
            for (int j = 0; j < 8; j++) {
                int idx = j * 128 + lt;           // 0..1023
                int b   = idx >> 5;
                int k   = kq + (idx & 31) * 4;
                const float* src = hsrcBase + b * U_DIM + k;
                unsigned dst = hs_s + (unsigned)(b * US_STR + k) * 4u;
                asm volatile("cp.async.cg.shared.global [%0], [%1], 16;" :: "r"(dst), "l"(src));
            }
            asm volatile("cp.async.commit_group;");
        }
        asm volatile("cp.async.wait_group 0;");
        asm volatile("bar.sync %0, 128;" :: "r"(1 + quarter));

        float c0f[4] = {0, 0, 0, 0}, c1f[4] = {0, 0, 0, 0};
        #pragma unroll 4
        for (int kb = 0; kb < 16; kb++) {
            int o = quarter * 128 + kb * 8 + 2 * tig;
            uint2 ar0 = *(const uint2*)(hrow0 + o);
            uint2 ar1 = *(const uint2*)(hrow1 + o);
            uint2 bu0 = *(const uint2*)(urow0 + o);
            uint2 bu1 = *(const uint2*)(urow1 + o);
            mma8(c0f, ar0.x, ar1.x, ar0.y, ar1.y, bu0.x, bu0.y);
            mma8(c1f, ar0.x, ar1.x, ar0.y, ar1.y, bu1.x, bu1.y);
        }

        // publish this quarter's partial preactivations
        *(float2*)&gpq[r0 * GP_STR + g0 * 8 + 2 * tig]       = make_float2(c0f[0], c0f[1]);
        *(float2*)&gpq[(r0 + 8) * GP_STR + g0 * 8 + 2 * tig] = make_float2(c0f[2], c0f[3]);
        *(float2*)&gpq[r0 * GP_STR + g1 * 8 + 2 * tig]       = make_float2(c1f[0], c1f[1]);
        *(float2*)&gpq[(r0 + 8) * GP_STR + g1 * 8 + 2 * tig] = make_float2(c1f[2], c1f[3]);
        __syncthreads();

        // epilogue (tid<256): reduce 4 quarters + xg, gates (i,f,c,o), update h
        float hv = 0.0f;
        if (tid < 256) {
            const float* p0 = gp + eb * GP_STR;
            const float* p1 = gp + (32 + eb) * GP_STR;
            const float* p2 = gp + (64 + eb) * GP_STR;
            const float* p3 = gp + (96 + eb) * GP_STR;
            float iv = fsigm(xr[0] + (p0[euu]      + p1[euu])      + (p2[euu]      + p3[euu]));
            float fv = fsigm(xr[1] + (p0[8 + euu]  + p1[8 + euu])  + (p2[8 + euu]  + p3[8 + euu]));
            float cc = ftanh(xr[2] + (p0[16 + euu] + p1[16 + euu]) + (p2[16 + euu] + p3[16 + euu]));
            float ov = fsigm(xr[3] + (p0[24 + euu] + p1[24 + euu]) + (p2[24 + euu] + p3[24 + euu]));
            cst = fv * cst + iv * cc;
            hv = ov * ftanh(cst);
            g_hbuf[dir][buf ^ 1][eb][u0 + ((euu & 3) << 1) + (euu >> 2)] = tf32f(hv);
        }
        __syncthreads();

        // arrive (release our slice of h(s+1)) BEFORE output stores
        if (tid == 0) ch_arrive(dir, chunk, ep0 + 2u + (unsigned)s);

        // merge into zero-initialized out (order-free across directions)
        if (tid < 256)
            red_add(out + ((size_t)eb * T_SEQ + tt) * U_DIM + u0 + euu, hv);
    }
}

// =================================================================================
extern "C" void kernel_launch(void* const* d_in, const int* in_sizes, int n_in,
                              void* d_out, int out_size)
{
    const float* x  = (const float*)d_in[0];
    const float* z  = (const float*)d_in[1];
    const float* Wf = (const float*)d_in[2];
    const float* Uf = (const float*)d_in[3];
    const float* bf = (const float*)d_in[4];
    const float* Wb = (const float*)d_in[5];
    const float* Ub = (const float*)d_in[6];
    const float* bb = (const float*)d_in[7];
    float* out = (float*)d_out;

    cudaFuncSetAttribute(gemm_xg, cudaFuncAttributeMaxDynamicSharedMemorySize, GSMEM);
    cudaFuncSetAttribute(lstm_rec, cudaFuncAttributeMaxDynamicSharedMemorySize, SMEM_REC);

    // pre-passes: tf32-rounded x (transposed) + W copies; zero out for RED merge
    cvt_xT<<<dim3(D_DIM / 32, M_TOT / 32), dim3(32, 8)>>>(x);
    {
        int total4 = 2 * D_DIM * NG / 4;
        cvt_W<<<(total4 + 255) / 256, 256>>>(Wf, Wb);
    }
    cudaMemsetAsync(out, 0, (size_t)out_size * sizeof(float), 0);

    gemm_xg<<<4096, 256, GSMEM>>>(bf, bb);
    lstm_rec<<<2 * NCTA_DIR, REC_THREADS, SMEM_REC>>>(z, Uf, Ub, out);
}